// round 5
// baseline (speedup 1.0000x reference)
#include <cuda_runtime.h>

// Problem shape (fixed by reference setup_inputs): B=32, F=1024, J=22
#define BB   32
#define FF   1024
#define NJ   22
#define NSEG 16     // total segments across the 5 paths: 3+3+4+3+3
#define NPP  25     // 5x5 path pairs

// Scratch: gli[B, F, 25]  (3.27 MB) — static device global (no allocation)
__device__ float g_gli[BB * FF * NPP];

// Segment endpoint joint indices (from KINEMATIC_CHAIN paths)
// path0: 2-5-8-11 | path1: 1-4-7-10 | path2: 3-6-9-12-15 | path3: 14-17-19-21 | path4: 13-16-18-20
__constant__ int c_segA[NSEG] = {2,5,8,  1,4,7,  3,6,9,12,  14,17,19,  13,16,18};
__constant__ int c_segB[NSEG] = {5,8,11, 4,7,10, 6,9,12,15, 17,19,21,  16,18,20};
__constant__ int c_pstart[5]  = {0,3,6,10,13};
__constant__ int c_pcnt[5]    = {3,3,4,3,3};

struct V3 { float x, y, z; };

__device__ __forceinline__ V3 v_sub(V3 a, V3 b) {
    return {a.x - b.x, a.y - b.y, a.z - b.z};
}
__device__ __forceinline__ V3 v_crs(V3 a, V3 b) {
    return {a.y * b.z - a.z * b.y,
            a.z * b.x - a.x * b.z,
            a.x * b.y - a.y * b.x};
}
__device__ __forceinline__ float v_dot(V3 a, V3 b) {
    return a.x * b.x + a.y * b.y + a.z * b.z;
}

// One block per (b,f) frame pair. 256 threads = one per (seg_i, seg_j) pair.
__global__ void __launch_bounds__(256, 8)
gli_kernel(const float* __restrict__ m1, const float* __restrict__ m2) {
    __shared__ float sm1[NJ * 3];
    __shared__ float sm2[NJ * 3];
    __shared__ float g[256];

    const int bf = blockIdx.x;                 // b*F + f
    const int t  = threadIdx.x;

    // Stage both frames' joints (66 floats each) into shared memory.
    const float* p1 = m1 + (size_t)bf * (NJ * 3);
    const float* p2 = m2 + (size_t)bf * (NJ * 3);
    if (t < NJ * 3)            sm1[t]          = p1[t];
    else if (t < 2 * NJ * 3)   sm2[t - NJ * 3] = p2[t - NJ * 3];
    __syncthreads();

    const int i = t >> 4;      // segment index in motion1
    const int j = t & 15;      // segment index in motion2

    const int a1 = 3 * c_segA[i], b1 = 3 * c_segB[i];
    const int a2 = 3 * c_segA[j], b2 = 3 * c_segB[j];

    V3 s1 = {sm1[a1], sm1[a1 + 1], sm1[a1 + 2]};
    V3 e1 = {sm1[b1], sm1[b1 + 1], sm1[b1 + 2]};
    V3 s2 = {sm2[a2], sm2[a2 + 1], sm2[a2 + 2]};
    V3 e2 = {sm2[b2], sm2[b2 + 1], sm2[b2 + 2]};

    V3 r13 = v_sub(s2, s1);
    V3 r14 = v_sub(e2, s1);
    V3 r23 = v_sub(s2, e1);
    V3 r24 = v_sub(e2, e1);
    V3 r12 = v_sub(e1, s1);
    V3 r34 = v_sub(e2, s2);

    V3 f0 = v_crs(r13, r14);
    V3 f1 = v_crs(r14, r24);
    V3 f2 = v_crs(r24, r23);
    V3 f3 = v_crs(r23, r13);

    float n0 = v_dot(f0, f0);
    float n1 = v_dot(f1, f1);
    float n2 = v_dot(f2, f2);
    float n3 = v_dot(f3, f3);

    float i0 = (n0 > 0.f) ? rsqrtf(n0) : 0.f;
    float i1 = (n1 > 0.f) ? rsqrtf(n1) : 0.f;
    float i2 = (n2 > 0.f) ? rsqrtf(n2) : 0.f;
    float i3 = (n3 > 0.f) ? rsqrtf(n3) : 0.f;

    // dots between consecutive normalized face normals (roll -1)
    float d0 = v_dot(f0, f1) * (i0 * i1);
    float d1 = v_dot(f1, f2) * (i1 * i2);
    float d2 = v_dot(f2, f3) * (i2 * i3);
    float d3 = v_dot(f3, f0) * (i3 * i0);

    const float CL = 1.0f - 1e-7f;
    d0 = fminf(fmaxf(d0, -CL), CL);
    d1 = fminf(fmaxf(d1, -CL), CL);
    d2 = fminf(fmaxf(d2, -CL), CL);
    d3 = fminf(fmaxf(d3, -CL), CL);

    float gl = asinf(d0) + asinf(d1) + asinf(d2) + asinf(d3);

    float sg = v_dot(v_crs(r34, r12), r13);
    gl = (sg <= 0.f) ? -gl : gl;

    g[t] = gl * 0.07957747154594767f;   // 1/(4*pi)
    __syncthreads();

    // Segmented reduction: 25 path pairs, each a rectangular sub-block of g.
    if (t < NPP) {
        const int P1 = t / 5;
        const int P2 = t - P1 * 5;
        const int o1 = c_pstart[P1], c1 = c_pcnt[P1];
        const int o2 = c_pstart[P2], c2 = c_pcnt[P2];
        float s = 0.f;
        for (int ii = 0; ii < c1; ii++) {
            const float* row = &g[(o1 + ii) * 16 + o2];
            for (int jj = 0; jj < c2; jj++) s += row[jj];
        }
        g_gli[(size_t)bf * NPP + t] = s;
    }
}

// out[b, f] = max_pp | gli[b, f+1, pp] - gli[b, f, pp] |
__global__ void vel_kernel(float* __restrict__ out) {
    const int FM1 = FF - 1;
    const int idx = blockIdx.x * blockDim.x + threadIdx.x;
    if (idx >= BB * FM1) return;
    const int b = idx / FM1;
    const int f = idx - b * FM1;
    const float* a = g_gli + ((size_t)b * FF + f) * NPP;
    float m = 0.f;
#pragma unroll
    for (int k = 0; k < NPP; k++) {
        m = fmaxf(m, fabsf(a[k + NPP] - a[k]));
    }
    out[idx] = m;
}

extern "C" void kernel_launch(void* const* d_in, const int* in_sizes, int n_in,
                              void* d_out, int out_size) {
    const float* m1 = (const float*)d_in[0];
    const float* m2 = (const float*)d_in[1];
    float* out = (float*)d_out;

    gli_kernel<<<BB * FF, 256>>>(m1, m2);

    const int total = BB * (FF - 1);
    vel_kernel<<<(total + 255) / 256, 256>>>(out);
}

// round 7
// speedup vs baseline: 1.3065x; 1.3065x over previous
#include <cuda_runtime.h>

// Problem shape (fixed by reference setup_inputs): B=32, F=1024, J=22
#define BB   32
#define FF   1024
#define NJ   22
#define NSEG 16     // segments across the 5 paths: 3+3+4+3+3
#define NPP  25     // 5x5 path pairs

typedef unsigned long long u64;

// Scratch: gli[B, F, 25]  (3.27 MB) — static device global (no allocation)
__device__ float g_gli[BB * FF * NPP];

// Segment endpoint joint indices (from KINEMATIC_CHAIN paths)
__constant__ int c_segA[NSEG] = {2,5,8,  1,4,7,  3,6,9,12,  14,17,19,  13,16,18};
__constant__ int c_segB[NSEG] = {5,8,11, 4,7,10, 6,9,12,15, 17,19,21,  16,18,20};
__constant__ int c_pstart[5]  = {0,3,6,10,13};
__constant__ int c_pcnt[5]    = {3,3,4,3,3};

// ---------------- packed f32x2 helpers (sm_103a FFMA2 path) ----------------
__device__ __forceinline__ u64 f2(float lo, float hi) {
    u64 r; asm("mov.b64 %0, {%1, %2};" : "=l"(r) : "f"(lo), "f"(hi)); return r;
}
__device__ __forceinline__ u64 f2b(float v) { return f2(v, v); }
__device__ __forceinline__ void f2u(u64 a, float& lo, float& hi) {
    asm("mov.b64 {%0, %1}, %2;" : "=f"(lo), "=f"(hi) : "l"(a));
}
__device__ __forceinline__ u64 f2add(u64 a, u64 b) {
    u64 r; asm("add.rn.f32x2 %0, %1, %2;" : "=l"(r) : "l"(a), "l"(b)); return r;
}
__device__ __forceinline__ u64 f2mul(u64 a, u64 b) {
    u64 r; asm("mul.rn.f32x2 %0, %1, %2;" : "=l"(r) : "l"(a), "l"(b)); return r;
}
__device__ __forceinline__ u64 f2fma(u64 a, u64 b, u64 c) {
    u64 r; asm("fma.rn.f32x2 %0, %1, %2, %3;" : "=l"(r) : "l"(a), "l"(b), "l"(c)); return r;
}
// negate both lanes via sign-bit XOR (ALU pipe, off the FMA pipe)
__device__ __forceinline__ u64 f2neg(u64 a) { return a ^ 0x8000000080000000ULL; }
// a - b  ==  fma(b, -1, a): b*(-1) is exact, so rounding identical to sub
__device__ __forceinline__ u64 f2sub(u64 a, u64 b) { return f2fma(b, f2b(-1.0f), a); }

struct W3 { u64 x, y, z; };

__device__ __forceinline__ W3 w_sub(W3 a, W3 b) {
    return { f2sub(a.x, b.x), f2sub(a.y, b.y), f2sub(a.z, b.z) };
}
__device__ __forceinline__ W3 w_crs(W3 a, W3 b) {
    return { f2fma(a.y, b.z, f2neg(f2mul(a.z, b.y))),
             f2fma(a.z, b.x, f2neg(f2mul(a.x, b.z))),
             f2fma(a.x, b.y, f2neg(f2mul(a.y, b.x))) };
}
__device__ __forceinline__ u64 w_dot(W3 a, W3 b) {
    return f2fma(a.z, b.z, f2fma(a.y, b.y, f2mul(a.x, b.x)));
}

// asin(clip(d, ±(1-1e-7))) lanewise.
// Abramowitz-Stegun 4.4.46: asin(x) = pi/2 - sqrt(1-x) * P7(x), x in [0,1],
// |err| <= 2e-8.
__device__ __forceinline__ u64 f2_asin_clamped(u64 d) {
    const float CL = (float)(1.0 - 1e-7);      // 0.99999988f, matches jax fp32 clip
    float dlo, dhi;  f2u(d, dlo, dhi);
    float alo = fminf(fabsf(dlo), CL);
    float ahi = fminf(fabsf(dhi), CL);
    float hlo = 1.0f - alo;                    // >= 1.19e-7 > 0
    float hhi = 1.0f - ahi;
    float sqlo = hlo * rsqrtf(hlo);            // sqrt(h) via MUFU.RSQ
    float sqhi = hhi * rsqrtf(hhi);
    u64 A  = f2(alo, ahi);
    u64 SQ = f2(sqlo, sqhi);
    u64 p = f2fma(A, f2b(-0.0012624911f), f2b( 0.0066700901f));
    p = f2fma(A, p, f2b(-0.0170881256f));
    p = f2fma(A, p, f2b( 0.0308918810f));
    p = f2fma(A, p, f2b(-0.0501743046f));
    p = f2fma(A, p, f2b( 0.0889789874f));
    p = f2fma(A, p, f2b(-0.2145988016f));
    p = f2fma(A, p, f2b( 1.5707963050f));
    u64 t = f2fma(SQ, f2neg(p), f2b(1.57079632679f));   // both lanes >= 0
    return t | (d & 0x8000000080000000ULL);              // copysign(t, d) lanewise
}

// guarded reciprocal norm (matches reference where(norms>0, ..., 0))
__device__ __forceinline__ u64 f2_invnorm(u64 n) {
    float lo, hi;  f2u(n, lo, hi);
    float il = (lo > 0.f) ? rsqrtf(lo) : 0.f;
    float ih = (hi > 0.f) ? rsqrtf(hi) : 0.f;
    return f2(il, ih);
}

// ---------------------------------------------------------------------------
// One block = TWO consecutive frame pairs (lanes of the f32x2 packs).
// 256 threads = one per (seg_i, seg_j) pair; each thread handles both frames.
// ---------------------------------------------------------------------------
__global__ void __launch_bounds__(256)
gli_kernel(const float* __restrict__ m1, const float* __restrict__ m2) {
    __shared__ float sm1[2 * NJ * 3];
    __shared__ float sm2[2 * NJ * 3];
    __shared__ u64   g[256];

    const int bf0 = blockIdx.x * 2;            // first of the two frames
    const int t   = threadIdx.x;

    // Stage both frames (2 x 66 floats per motion = 132 each, 264 total) into
    // shared. 256 threads < 264 elements, so coverage must OVERLAP:
    //   threads   0..131 load sm1[0..131]
    //   threads 124..255 load sm2[0..131]   (t-124)
    // (R6 bug: disjoint if/else left sm2[124..131] — joints 20,21 of the hi
    //  frame — uninitialized.)
    const float* p1 = m1 + (size_t)bf0 * (NJ * 3);
    const float* p2 = m2 + (size_t)bf0 * (NJ * 3);
    if (t < 2 * NJ * 3)  sm1[t] = p1[t];
    if (t >= 124)        { const int u = t - 124; sm2[u] = p2[u]; }
    __syncthreads();

    const int i = t >> 4;
    const int j = t & 15;
    const int a1 = 3 * c_segA[i], b1 = 3 * c_segB[i];
    const int a2 = 3 * c_segA[j], b2 = 3 * c_segB[j];

    W3 s1 = { f2(sm1[a1    ], sm1[66 + a1    ]),
              f2(sm1[a1 + 1], sm1[66 + a1 + 1]),
              f2(sm1[a1 + 2], sm1[66 + a1 + 2]) };
    W3 e1 = { f2(sm1[b1    ], sm1[66 + b1    ]),
              f2(sm1[b1 + 1], sm1[66 + b1 + 1]),
              f2(sm1[b1 + 2], sm1[66 + b1 + 2]) };
    W3 s2 = { f2(sm2[a2    ], sm2[66 + a2    ]),
              f2(sm2[a2 + 1], sm2[66 + a2 + 1]),
              f2(sm2[a2 + 2], sm2[66 + a2 + 2]) };
    W3 e2 = { f2(sm2[b2    ], sm2[66 + b2    ]),
              f2(sm2[b2 + 1], sm2[66 + b2 + 1]),
              f2(sm2[b2 + 2], sm2[66 + b2 + 2]) };

    W3 r13 = w_sub(s2, s1);
    W3 r14 = w_sub(e2, s1);
    W3 r23 = w_sub(s2, e1);
    W3 r24 = w_sub(e2, e1);

    // sign term first (r12, r34 die immediately -> lower register pressure)
    u64 sg;
    {
        W3 r12 = w_sub(e1, s1);
        W3 r34 = w_sub(e2, s2);
        sg = w_dot(w_crs(r34, r12), r13);
    }

    W3 f0  = w_crs(r13, r14);
    W3 f1  = w_crs(r14, r24);
    W3 fc2 = w_crs(r24, r23);
    W3 f3  = w_crs(r23, r13);

    u64 I0 = f2_invnorm(w_dot(f0,  f0));
    u64 I1 = f2_invnorm(w_dot(f1,  f1));
    u64 I2 = f2_invnorm(w_dot(fc2, fc2));
    u64 I3 = f2_invnorm(w_dot(f3,  f3));

    u64 d0 = f2mul(w_dot(f0,  f1),  f2mul(I0, I1));
    u64 d1 = f2mul(w_dot(f1,  fc2), f2mul(I1, I2));
    u64 d2 = f2mul(w_dot(fc2, f3),  f2mul(I2, I3));
    u64 d3 = f2mul(w_dot(f3,  f0),  f2mul(I3, I0));

    u64 gl = f2add(f2add(f2_asin_clamped(d0), f2_asin_clamped(d1)),
                   f2add(f2_asin_clamped(d2), f2_asin_clamped(d3)));

    // sign <= 0  ->  negate; scale by 1/(4*pi)
    {
        const float INV4PI = 0.07957747154594767f;
        float glo, ghi, slo, shi;
        f2u(gl, glo, ghi);
        f2u(sg, slo, shi);
        glo = ((slo <= 0.f) ? -glo : glo) * INV4PI;
        ghi = ((shi <= 0.f) ? -ghi : ghi) * INV4PI;
        g[t] = f2(glo, ghi);
    }
    __syncthreads();

    // Segmented reduction: 25 path pairs, packed adds over both frames at once.
    if (t < NPP) {
        const int P1 = t / 5;
        const int P2 = t - P1 * 5;
        const int o1 = c_pstart[P1], cn1 = c_pcnt[P1];
        const int o2 = c_pstart[P2], cn2 = c_pcnt[P2];
        u64 s = f2b(0.0f);
        for (int ii = 0; ii < cn1; ii++) {
            const u64* row = &g[(o1 + ii) * 16 + o2];
            for (int jj = 0; jj < cn2; jj++) s = f2add(s, row[jj]);
        }
        float slo, shi;  f2u(s, slo, shi);
        // contiguous 50-float window across the two frames -> coalesced
        g_gli[(size_t)bf0 * NPP + t]       = slo;
        g_gli[(size_t)bf0 * NPP + NPP + t] = shi;
    }
}

// out[b, f] = max_pp | gli[b, f+1, pp] - gli[b, f, pp] | — one warp per output
__global__ void vel_kernel(float* __restrict__ out) {
    const int FM1 = FF - 1;
    const int w    = (blockIdx.x * blockDim.x + threadIdx.x) >> 5;
    const int lane = threadIdx.x & 31;
    if (w >= BB * FM1) return;
    const int b = w / FM1;
    const int f = w - b * FM1;
    const float* a = g_gli + ((size_t)b * FF + f) * NPP;
    float v = 0.f;
    if (lane < NPP) v = fabsf(a[lane + NPP] - a[lane]);
#pragma unroll
    for (int s = 16; s > 0; s >>= 1)
        v = fmaxf(v, __shfl_xor_sync(0xffffffffu, v, s));
    if (lane == 0) out[w] = v;
}

extern "C" void kernel_launch(void* const* d_in, const int* in_sizes, int n_in,
                              void* d_out, int out_size) {
    const float* m1 = (const float*)d_in[0];
    const float* m2 = (const float*)d_in[1];
    float* out = (float*)d_out;

    gli_kernel<<<BB * FF / 2, 256>>>(m1, m2);

    const int total_warps = BB * (FF - 1);           // 32736
    const int threads = total_warps * 32;
    vel_kernel<<<(threads + 255) / 256, 256>>>(out);
}

// round 9
// speedup vs baseline: 1.5017x; 1.1494x over previous
#include <cuda_runtime.h>

// Problem shape (fixed by reference setup_inputs): B=32, F=1024, J=22
#define BB   32
#define FF   1024
#define NJ   22
#define NSEG 16     // segments across the 5 paths: 3+3+4+3+3
#define NPP  25     // 5x5 path pairs
#define FM1  (FF - 1)

typedef unsigned long long u64;

// Scratch: gli[B, F, 25]  (3.27 MB) — static device global (no allocation)
__device__ float g_gli[BB * FF * NPP];

// Segment endpoint joint indices (from KINEMATIC_CHAIN paths)
__constant__ int c_segA[NSEG] = {2,5,8,  1,4,7,  3,6,9,12,  14,17,19,  13,16,18};
__constant__ int c_segB[NSEG] = {5,8,11, 4,7,10, 6,9,12,15, 17,19,21,  16,18,20};
__constant__ int c_pstart[5]  = {0,3,6,10,13};
__constant__ int c_pcnt[5]    = {3,3,4,3,3};

// ---------------- packed f32x2 helpers (sm_103a FFMA2 path) ----------------
__device__ __forceinline__ u64 f2(float lo, float hi) {
    u64 r; asm("mov.b64 %0, {%1, %2};" : "=l"(r) : "f"(lo), "f"(hi)); return r;
}
__device__ __forceinline__ u64 f2b(float v) { return f2(v, v); }
__device__ __forceinline__ void f2u(u64 a, float& lo, float& hi) {
    asm("mov.b64 {%0, %1}, %2;" : "=f"(lo), "=f"(hi) : "l"(a));
}
__device__ __forceinline__ u64 f2add(u64 a, u64 b) {
    u64 r; asm("add.rn.f32x2 %0, %1, %2;" : "=l"(r) : "l"(a), "l"(b)); return r;
}
__device__ __forceinline__ u64 f2mul(u64 a, u64 b) {
    u64 r; asm("mul.rn.f32x2 %0, %1, %2;" : "=l"(r) : "l"(a), "l"(b)); return r;
}
__device__ __forceinline__ u64 f2fma(u64 a, u64 b, u64 c) {
    u64 r; asm("fma.rn.f32x2 %0, %1, %2, %3;" : "=l"(r) : "l"(a), "l"(b), "l"(c)); return r;
}
// negate both lanes via sign-bit XOR (ALU pipe, off the FMA pipe)
__device__ __forceinline__ u64 f2neg(u64 a) { return a ^ 0x8000000080000000ULL; }
// a - b == fma(b, -1, a): b*(-1) exact, rounding identical to sub
__device__ __forceinline__ u64 f2sub(u64 a, u64 b) { return f2fma(b, f2b(-1.0f), a); }

struct W3 { u64 x, y, z; };

__device__ __forceinline__ W3 w_sub(W3 a, W3 b) {
    return { f2sub(a.x, b.x), f2sub(a.y, b.y), f2sub(a.z, b.z) };
}
__device__ __forceinline__ W3 w_add(W3 a, W3 b) {
    return { f2add(a.x, b.x), f2add(a.y, b.y), f2add(a.z, b.z) };
}
__device__ __forceinline__ W3 w_crs(W3 a, W3 b) {
    return { f2fma(a.y, b.z, f2neg(f2mul(a.z, b.y))),
             f2fma(a.z, b.x, f2neg(f2mul(a.x, b.z))),
             f2fma(a.x, b.y, f2neg(f2mul(a.y, b.x))) };
}
__device__ __forceinline__ u64 w_dot(W3 a, W3 b) {
    return f2fma(a.z, b.z, f2fma(a.y, b.y, f2mul(a.x, b.x)));
}

// lanewise rsqrt with zero-guard (norms-product path)
__device__ __forceinline__ u64 f2_rnorm(u64 n) {
    float lo, hi;  f2u(n, lo, hi);
    float il = rsqrtf(fmaxf(lo, 1e-30f));
    float ih = rsqrtf(fmaxf(hi, 1e-30f));
    return f2(il, ih);
}

// asin(clip(d, ±(1-1e-7))) lanewise.
// Abramowitz-Stegun 4.4.46: asin(x) = pi/2 - sqrt(1-x)*P7(x), |err| <= 2e-8.
__device__ __forceinline__ u64 f2_asin_clamped(u64 d) {
    const float CL = (float)(1.0 - 1e-7);      // 0.99999988f = fp32 of jax clip
    float dlo, dhi;  f2u(d, dlo, dhi);
    float alo = fminf(fabsf(dlo), CL);
    float ahi = fminf(fabsf(dhi), CL);
    float hlo = 1.0f - alo;                    // >= 1.19e-7 > 0
    float hhi = 1.0f - ahi;
    float sqlo = hlo * rsqrtf(hlo);            // sqrt(h) via MUFU.RSQ
    float sqhi = hhi * rsqrtf(hhi);
    u64 A  = f2(alo, ahi);
    u64 SQ = f2(sqlo, sqhi);
    u64 p = f2fma(A, f2b(-0.0012624911f), f2b( 0.0066700901f));
    p = f2fma(A, p, f2b(-0.0170881256f));
    p = f2fma(A, p, f2b( 0.0308918810f));
    p = f2fma(A, p, f2b(-0.0501743046f));
    p = f2fma(A, p, f2b( 0.0889789874f));
    p = f2fma(A, p, f2b(-0.2145988016f));
    p = f2fma(A, p, f2b( 1.5707963050f));
    u64 t = f2fma(SQ, f2neg(p), f2b(1.57079632679f));   // both lanes >= 0
    return t | (d & 0x8000000080000000ULL);              // copysign(t, d)
}

// ---------------------------------------------------------------------------
// One block = TWO consecutive frame pairs (lanes of the f32x2 packs).
// 256 threads = one per (seg_i, seg_j) pair; each thread handles both frames.
//
// Face normals via 3-cross identity (r14 = r13+r34, r23 = r13-r12,
// r24 = r13+r34-r12):
//   C1 = r13xr34, C2 = r13xr12, C3 = r34xr12
//   f0 = C1, f1 = -(C2+C3), f2 = -(C1+C3), f3 = C2, sign = C3.r13
// ---------------------------------------------------------------------------
__global__ void __launch_bounds__(256)
gli_kernel(const float* __restrict__ m1, const float* __restrict__ m2) {
    __shared__ float sm1[2 * NJ * 3];
    __shared__ float sm2[2 * NJ * 3];
    __shared__ u64   g[256];

    const int bf0 = blockIdx.x * 2;            // first of the two frames
    const int t   = threadIdx.x;

    // Stage 2 frames per motion (132 floats each; 264 total > 256 threads,
    // so coverage overlaps: t<132 -> sm1[t], t>=124 -> sm2[t-124]).
    const float* p1 = m1 + (size_t)bf0 * (NJ * 3);
    const float* p2 = m2 + (size_t)bf0 * (NJ * 3);
    if (t < 2 * NJ * 3)  sm1[t] = p1[t];
    if (t >= 124)        { const int u = t - 124; sm2[u] = p2[u]; }
    __syncthreads();

    const int i = t >> 4;
    const int j = t & 15;
    const int a1 = 3 * c_segA[i], b1 = 3 * c_segB[i];
    const int a2 = 3 * c_segA[j], b2 = 3 * c_segB[j];

    W3 s1 = { f2(sm1[a1    ], sm1[66 + a1    ]),
              f2(sm1[a1 + 1], sm1[66 + a1 + 1]),
              f2(sm1[a1 + 2], sm1[66 + a1 + 2]) };
    W3 e1 = { f2(sm1[b1    ], sm1[66 + b1    ]),
              f2(sm1[b1 + 1], sm1[66 + b1 + 1]),
              f2(sm1[b1 + 2], sm1[66 + b1 + 2]) };
    W3 s2 = { f2(sm2[a2    ], sm2[66 + a2    ]),
              f2(sm2[a2 + 1], sm2[66 + a2 + 1]),
              f2(sm2[a2 + 2], sm2[66 + a2 + 2]) };
    W3 e2 = { f2(sm2[b2    ], sm2[66 + b2    ]),
              f2(sm2[b2 + 1], sm2[66 + b2 + 1]),
              f2(sm2[b2 + 2], sm2[66 + b2 + 2]) };

    W3 r13 = w_sub(s2, s1);
    W3 r12 = w_sub(e1, s1);
    W3 r34 = w_sub(e2, s2);

    W3 C1 = w_crs(r13, r34);
    W3 C2 = w_crs(r13, r12);
    W3 C3 = w_crs(r34, r12);

    u64 sg = w_dot(C3, r13);       // sign term: cross(r34,r12).r13

    W3 S23 = w_add(C2, C3);        // -f1
    W3 S13 = w_add(C1, C3);        // -f2

    u64 n0 = w_dot(C1,  C1);       // |f0|^2
    u64 n1 = w_dot(S23, S23);      // |f1|^2
    u64 n2 = w_dot(S13, S13);      // |f2|^2
    u64 n3 = w_dot(C2,  C2);       // |f3|^2

    u64 t01 = w_dot(C1,  S23);     // f0.f1 = -t01
    u64 t12 = w_dot(S23, S13);     // f1.f2 = +t12
    u64 t23 = w_dot(S13, C2);      // f2.f3 = -t23
    u64 t30 = w_dot(C2,  C1);      // f3.f0 = +t30

    u64 u01 = f2mul(t01, f2_rnorm(f2mul(n0, n1)));
    u64 u12 = f2mul(t12, f2_rnorm(f2mul(n1, n2)));
    u64 u23 = f2mul(t23, f2_rnorm(f2mul(n2, n3)));
    u64 u30 = f2mul(t30, f2_rnorm(f2mul(n3, n0)));

    // gli = asin(-u01) + asin(u12) + asin(-u23) + asin(u30)
    u64 gl = f2add(f2add(f2_asin_clamped(u12), f2_asin_clamped(u30)),
                   f2neg(f2add(f2_asin_clamped(u01), f2_asin_clamped(u23))));

    // sign <= 0 -> negate; scale by 1/(4*pi)
    {
        const float INV4PI = 0.07957747154594767f;
        float glo, ghi, slo, shi;
        f2u(gl, glo, ghi);
        f2u(sg, slo, shi);
        glo = ((slo <= 0.f) ? -glo : glo) * INV4PI;
        ghi = ((shi <= 0.f) ? -ghi : ghi) * INV4PI;
        g[t] = f2(glo, ghi);
    }
    __syncthreads();

    // Segmented reduction: 25 path pairs, packed adds over both frames.
    if (t < NPP) {
        const int P1 = t / 5;
        const int P2 = t - P1 * 5;
        const int o1 = c_pstart[P1], cn1 = c_pcnt[P1];
        const int o2 = c_pstart[P2], cn2 = c_pcnt[P2];
        u64 s = f2b(0.0f);
        for (int ii = 0; ii < cn1; ii++) {
            const u64* row = &g[(o1 + ii) * 16 + o2];
            for (int jj = 0; jj < cn2; jj++) s = f2add(s, row[jj]);
        }
        float slo, shi;  f2u(s, slo, shi);
        g_gli[(size_t)bf0 * NPP + t]       = slo;
        g_gli[(size_t)bf0 * NPP + NPP + t] = shi;
    }
}

// out[b, f] = max_pp | gli[b, f+1, pp] - gli[b, f, pp] |
// Block-tiled: each block stages up to 257 frames' gli (25 floats each)
// through shared memory — every gli value read from L2 exactly once,
// fully coalesced. Grid = 32 b-values x 4 f-tiles = 128 blocks.
__global__ void __launch_bounds__(256)
vel_kernel(float* __restrict__ out) {
    __shared__ float sg[257 * NPP];
    const int b  = blockIdx.x >> 2;
    const int f0 = (blockIdx.x & 3) * 256;
    const int nf    = min(257, FF  - f0);     // frames staged (257 or 256)
    const int n_out = min(256, FM1 - f0);     // outputs (256 or 255)

    const float* src = g_gli + ((size_t)b * FF + f0) * NPP;
    const int tot = nf * NPP;
    for (int idx = threadIdx.x; idx < tot; idx += 256) sg[idx] = src[idx];
    __syncthreads();

    const int t = threadIdx.x;
    if (t < n_out) {
        const float* a = sg + t * NPP;
        float m = 0.f;
#pragma unroll
        for (int k = 0; k < NPP; k++)
            m = fmaxf(m, fabsf(a[k + NPP] - a[k]));
        out[b * FM1 + f0 + t] = m;
    }
}

extern "C" void kernel_launch(void* const* d_in, const int* in_sizes, int n_in,
                              void* d_out, int out_size) {
    const float* m1 = (const float*)d_in[0];
    const float* m2 = (const float*)d_in[1];
    float* out = (float*)d_out;

    gli_kernel<<<BB * FF / 2, 256>>>(m1, m2);
    vel_kernel<<<BB * 4, 256>>>(out);
}

// round 10
// speedup vs baseline: 1.7757x; 1.1824x over previous
#include <cuda_runtime.h>

// Problem shape (fixed by reference setup_inputs): B=32, F=1024, J=22
#define BB   32
#define FF   1024
#define NJ   22
#define NSEG 16     // segments across the 5 paths: 3+3+4+3+3
#define NPP  25     // 5x5 path pairs
#define FM1  (FF - 1)

#define GPB  4                      // f32x2 groups per block (8 frames)
#define FPB  (2 * GPB)              // frames per block
#define JF   (NJ * 3)               // 66 floats per frame

typedef unsigned long long u64;

// Scratch: gli[B, F, 25]  (3.27 MB) — static device global (no allocation)
__device__ float g_gli[BB * FF * NPP];

// Segment endpoint joint indices (from KINEMATIC_CHAIN paths)
__constant__ int c_segA[NSEG] = {2,5,8,  1,4,7,  3,6,9,12,  14,17,19,  13,16,18};
__constant__ int c_segB[NSEG] = {5,8,11, 4,7,10, 6,9,12,15, 17,19,21,  16,18,20};
__constant__ int c_pstart[5]  = {0,3,6,10,13};
__constant__ int c_pcnt[5]    = {3,3,4,3,3};

// ---------------- packed f32x2 helpers (sm_103a FFMA2 path) ----------------
__device__ __forceinline__ u64 f2(float lo, float hi) {
    u64 r; asm("mov.b64 %0, {%1, %2};" : "=l"(r) : "f"(lo), "f"(hi)); return r;
}
__device__ __forceinline__ u64 f2b(float v) { return f2(v, v); }
__device__ __forceinline__ void f2u(u64 a, float& lo, float& hi) {
    asm("mov.b64 {%0, %1}, %2;" : "=f"(lo), "=f"(hi) : "l"(a));
}
__device__ __forceinline__ u64 f2add(u64 a, u64 b) {
    u64 r; asm("add.rn.f32x2 %0, %1, %2;" : "=l"(r) : "l"(a), "l"(b)); return r;
}
__device__ __forceinline__ u64 f2mul(u64 a, u64 b) {
    u64 r; asm("mul.rn.f32x2 %0, %1, %2;" : "=l"(r) : "l"(a), "l"(b)); return r;
}
__device__ __forceinline__ u64 f2fma(u64 a, u64 b, u64 c) {
    u64 r; asm("fma.rn.f32x2 %0, %1, %2, %3;" : "=l"(r) : "l"(a), "l"(b), "l"(c)); return r;
}
// negate both lanes via sign-bit XOR (ALU pipe, off the FMA pipe)
__device__ __forceinline__ u64 f2neg(u64 a) { return a ^ 0x8000000080000000ULL; }
// a - b == fma(b, -1, a): b*(-1) exact, rounding identical to sub
__device__ __forceinline__ u64 f2sub(u64 a, u64 b) { return f2fma(b, f2b(-1.0f), a); }

struct W3 { u64 x, y, z; };

__device__ __forceinline__ W3 w_sub(W3 a, W3 b) {
    return { f2sub(a.x, b.x), f2sub(a.y, b.y), f2sub(a.z, b.z) };
}
__device__ __forceinline__ W3 w_add(W3 a, W3 b) {
    return { f2add(a.x, b.x), f2add(a.y, b.y), f2add(a.z, b.z) };
}
__device__ __forceinline__ W3 w_crs(W3 a, W3 b) {
    return { f2fma(a.y, b.z, f2neg(f2mul(a.z, b.y))),
             f2fma(a.z, b.x, f2neg(f2mul(a.x, b.z))),
             f2fma(a.x, b.y, f2neg(f2mul(a.y, b.x))) };
}
__device__ __forceinline__ u64 w_dot(W3 a, W3 b) {
    return f2fma(a.z, b.z, f2fma(a.y, b.y, f2mul(a.x, b.x)));
}

// lanewise rsqrt with zero-guard (norms-product path)
__device__ __forceinline__ u64 f2_rnorm(u64 n) {
    float lo, hi;  f2u(n, lo, hi);
    float il = rsqrtf(fmaxf(lo, 1e-30f));
    float ih = rsqrtf(fmaxf(hi, 1e-30f));
    return f2(il, ih);
}

// asin(clip(d, ±(1-1e-7))) lanewise.
// Abramowitz-Stegun 4.4.46: asin(x) = pi/2 - sqrt(1-x)*P7(x), |err| <= 2e-8.
__device__ __forceinline__ u64 f2_asin_clamped(u64 d) {
    const float CL = (float)(1.0 - 1e-7);      // 0.99999988f = fp32 of jax clip
    float dlo, dhi;  f2u(d, dlo, dhi);
    float alo = fminf(fabsf(dlo), CL);
    float ahi = fminf(fabsf(dhi), CL);
    float hlo = 1.0f - alo;                    // >= 1.19e-7 > 0
    float hhi = 1.0f - ahi;
    float sqlo = hlo * rsqrtf(hlo);            // sqrt(h) via MUFU.RSQ
    float sqhi = hhi * rsqrtf(hhi);
    u64 A  = f2(alo, ahi);
    u64 SQ = f2(sqlo, sqhi);
    u64 p = f2fma(A, f2b(-0.0012624911f), f2b( 0.0066700901f));
    p = f2fma(A, p, f2b(-0.0170881256f));
    p = f2fma(A, p, f2b( 0.0308918810f));
    p = f2fma(A, p, f2b(-0.0501743046f));
    p = f2fma(A, p, f2b( 0.0889789874f));
    p = f2fma(A, p, f2b(-0.2145988016f));
    p = f2fma(A, p, f2b( 1.5707963050f));
    u64 t = f2fma(SQ, f2neg(p), f2b(1.57079632679f));   // both lanes >= 0
    return t | (d & 0x8000000080000000ULL);              // copysign(t, d)
}

// ---------------------------------------------------------------------------
// One block = FOUR f32x2 groups = 8 consecutive frame pairs.
// 256 threads = one per (seg_i, seg_j) pair; loop over groups; single
// __syncthreads pair; reduction by 100 threads (4 groups x 25 path pairs).
//
// Face normals via 3-cross identity (r14 = r13+r34, r23 = r13-r12,
// r24 = r13+r34-r12):
//   C1 = r13xr34, C2 = r13xr12, C3 = r34xr12
//   f0 = C1, f1 = -(C2+C3), f2 = -(C1+C3), f3 = C2, sign = C3.r13
// ---------------------------------------------------------------------------
__global__ void __launch_bounds__(256)
gli_kernel(const float* __restrict__ m1, const float* __restrict__ m2) {
    __shared__ float sj1[FPB * JF];       // 528 floats
    __shared__ float sj2[FPB * JF];       // 528 floats
    __shared__ u64   g[GPB * 256];        // 8 KB

    const int bf0 = blockIdx.x * FPB;     // first of the 8 frames
    const int t   = threadIdx.x;

    // Stage 8 frames per motion, fully coalesced.
    const float* p1 = m1 + (size_t)bf0 * JF;
    const float* p2 = m2 + (size_t)bf0 * JF;
    for (int idx = t; idx < FPB * JF; idx += 256) {
        sj1[idx] = p1[idx];
        sj2[idx] = p2[idx];
    }
    __syncthreads();

    const int i = t >> 4;
    const int j = t & 15;
    const int a1 = 3 * c_segA[i], b1 = 3 * c_segB[i];
    const int a2 = 3 * c_segA[j], b2 = 3 * c_segB[j];

#pragma unroll 1
    for (int k = 0; k < GPB; k++) {
        const float* q1 = sj1 + k * (2 * JF);   // lo frame; hi frame at +66
        const float* q2 = sj2 + k * (2 * JF);

        W3 s1 = { f2(q1[a1], q1[JF + a1]), f2(q1[a1+1], q1[JF + a1+1]), f2(q1[a1+2], q1[JF + a1+2]) };
        W3 e1 = { f2(q1[b1], q1[JF + b1]), f2(q1[b1+1], q1[JF + b1+1]), f2(q1[b1+2], q1[JF + b1+2]) };
        W3 s2 = { f2(q2[a2], q2[JF + a2]), f2(q2[a2+1], q2[JF + a2+1]), f2(q2[a2+2], q2[JF + a2+2]) };
        W3 e2 = { f2(q2[b2], q2[JF + b2]), f2(q2[b2+1], q2[JF + b2+1]), f2(q2[b2+2], q2[JF + b2+2]) };

        W3 r13 = w_sub(s2, s1);
        W3 r12 = w_sub(e1, s1);
        W3 r34 = w_sub(e2, s2);

        W3 C1 = w_crs(r13, r34);
        W3 C2 = w_crs(r13, r12);
        W3 C3 = w_crs(r34, r12);

        u64 sg = w_dot(C3, r13);       // sign term: cross(r34,r12).r13

        W3 S23 = w_add(C2, C3);        // -f1
        W3 S13 = w_add(C1, C3);        // -f2

        u64 n0 = w_dot(C1,  C1);       // |f0|^2
        u64 n1 = w_dot(S23, S23);      // |f1|^2
        u64 n2 = w_dot(S13, S13);      // |f2|^2
        u64 n3 = w_dot(C2,  C2);       // |f3|^2

        u64 t01 = w_dot(C1,  S23);     // f0.f1 = -t01
        u64 t12 = w_dot(S23, S13);     // f1.f2 = +t12
        u64 t23 = w_dot(S13, C2);      // f2.f3 = -t23
        u64 t30 = w_dot(C2,  C1);      // f3.f0 = +t30

        u64 u01 = f2mul(t01, f2_rnorm(f2mul(n0, n1)));
        u64 u12 = f2mul(t12, f2_rnorm(f2mul(n1, n2)));
        u64 u23 = f2mul(t23, f2_rnorm(f2mul(n2, n3)));
        u64 u30 = f2mul(t30, f2_rnorm(f2mul(n3, n0)));

        // gli = asin(-u01) + asin(u12) + asin(-u23) + asin(u30)
        u64 gl = f2add(f2add(f2_asin_clamped(u12), f2_asin_clamped(u30)),
                       f2neg(f2add(f2_asin_clamped(u01), f2_asin_clamped(u23))));

        // sign <= 0 -> negate; scale by 1/(4*pi)
        const float INV4PI = 0.07957747154594767f;
        float glo, ghi, slo, shi;
        f2u(gl, glo, ghi);
        f2u(sg, slo, shi);
        glo = ((slo <= 0.f) ? -glo : glo) * INV4PI;
        ghi = ((shi <= 0.f) ? -ghi : ghi) * INV4PI;
        g[k * 256 + t] = f2(glo, ghi);
    }
    __syncthreads();

    // Segmented reduction: 4 groups x 25 path pairs = 100 active threads.
    if (t < GPB * NPP) {
        const int q  = t / NPP;        // group
        const int pp = t - q * NPP;    // path pair
        const int P1 = pp / 5;
        const int P2 = pp - P1 * 5;
        const int o1 = c_pstart[P1], cn1 = c_pcnt[P1];
        const int o2 = c_pstart[P2], cn2 = c_pcnt[P2];
        const u64* gq = g + q * 256;
        u64 s = f2b(0.0f);
        for (int ii = 0; ii < cn1; ii++) {
            const u64* row = gq + (o1 + ii) * 16 + o2;
            for (int jj = 0; jj < cn2; jj++) s = f2add(s, row[jj]);
        }
        float slo, shi;  f2u(s, slo, shi);
        // block writes one contiguous 200-float window
        float* dst = g_gli + (size_t)(bf0 + 2 * q) * NPP + pp;
        dst[0]   = slo;
        dst[NPP] = shi;
    }
}

// out[b, f] = max_pp | gli[b, f+1, pp] - gli[b, f, pp] |
// 512 blocks (32 b-values x 16 f-tiles of 64 outputs): enough blocks to put
// >3 on every SM; each block stages 65 frames' gli through shared memory.
__global__ void __launch_bounds__(256)
vel_kernel(float* __restrict__ out) {
    __shared__ float sg[65 * NPP];
    const int b  = blockIdx.x >> 4;
    const int f0 = (blockIdx.x & 15) * 64;
    const int nf    = min(65, FF  - f0);      // frames staged (65, last tile 64)
    const int n_out = min(64, FM1 - f0);      // outputs (64, last tile 63)

    const float* src = g_gli + ((size_t)b * FF + f0) * NPP;
    const int tot = nf * NPP;
    for (int idx = threadIdx.x; idx < tot; idx += 256) sg[idx] = src[idx];
    __syncthreads();

    const int t = threadIdx.x;
    if (t < n_out) {
        const float* a = sg + t * NPP;
        float m = 0.f;
#pragma unroll
        for (int k = 0; k < NPP; k++)
            m = fmaxf(m, fabsf(a[k + NPP] - a[k]));
        out[b * FM1 + f0 + t] = m;
    }
}

extern "C" void kernel_launch(void* const* d_in, const int* in_sizes, int n_in,
                              void* d_out, int out_size) {
    const float* m1 = (const float*)d_in[0];
    const float* m2 = (const float*)d_in[1];
    float* out = (float*)d_out;

    gli_kernel<<<BB * FF / FPB, 256>>>(m1, m2);
    vel_kernel<<<BB * 16, 256>>>(out);
}